// round 4
// baseline (speedup 1.0000x reference)
#include <cuda_runtime.h>
#include <cuda_bf16.h>
#include <cstdint>

#define BATCH 64
#define NPIX  196
#define C1    2048
#define C2    512
#define KCONV 18432
#define K4    4096
#define EPSF  1e-6f
#define LDA   40   // smem row stride in bf16 elems (80B -> conflict-free frag loads)

// ---------------- scratch (device globals; no allocation) ----------------
__device__ float g_x [(size_t)BATCH * C2 * NPIX];   // conv+bn+relu output
__device__ float g_x2[(size_t)BATCH * C2 * NPIX];   // GCEM output
__device__ float g_zt[(size_t)BATCH * 8  * NPIX];   // attention maps
__device__ float g_x1[(size_t)BATCH * 4096 * NPIX]; // bkchv tensor
__device__ float g_t [(size_t)BATCH * C1 * NPIX];   // r5 * dic_global
__device__ float g_xb[(size_t)BATCH * C1 * NPIX];   // conv4(concat)
__device__ float g_xd[(size_t)BATCH * 32 * NPIX];   // downconv
__device__ float g_xc[(size_t)BATCH * NPIX];        // pooled attention scalar map

// ===========================================================================
// warp-MMA helpers (mma.sync bf16, sm_80+ PTX -> HMMA on sm_103)
// ===========================================================================
__device__ __forceinline__ void mma_bf16(float* d, const uint32_t* a, const uint32_t* b)
{
    asm volatile(
        "mma.sync.aligned.m16n8k16.row.col.f32.bf16.bf16.f32 "
        "{%0,%1,%2,%3}, {%4,%5,%6,%7}, {%8,%9}, {%0,%1,%2,%3};"
        : "+f"(d[0]), "+f"(d[1]), "+f"(d[2]), "+f"(d[3])
        : "r"(a[0]), "r"(a[1]), "r"(a[2]), "r"(a[3]), "r"(b[0]), "r"(b[1]));
}
__device__ __forceinline__ uint32_t lds32(const __nv_bfloat16* base, int elem)
{
    return *(const uint32_t*)(base + elem);
}
__device__ __forceinline__ void split_store(__nv_bfloat16* hi, __nv_bfloat16* lo,
                                            int idx, float v)
{
    __nv_bfloat16 h = __float2bfloat16(v);
    hi[idx] = h;
    lo[idx] = __float2bfloat16(v - __bfloat162float(h));
}

// ===========================================================================
// Unified big-GEMM kernel (block 128x128, kchunk 32, 8 warps of 64x32)
// MODE 0: conv4 pass1: A=c4w, B=x1,     out g_t  = r5*(acc+bias)
// MODE 1: conv4 pass2: A=c4w, B=[t;r5], out g_xb = acc+bias
// MODE 2: conv3x3:     A=fc0w, B=im2col(r5), out g_x = relu(BN(acc))
// ===========================================================================
template <int MODE>
__global__ void __launch_bounds__(256, 1) mma_gemm_kernel(
    const float* __restrict__ A, const float* __restrict__ r5,
    const float* __restrict__ bias,
    const float* __restrict__ gamma, const float* __restrict__ beta,
    const float* __restrict__ mean,  const float* __restrict__ var)
{
    constexpr int KTOT = (MODE == 2) ? KCONV : K4;

    __shared__ __nv_bfloat16 sAh[128 * LDA];
    __shared__ __nv_bfloat16 sAl[128 * LDA];
    __shared__ __nv_bfloat16 sBh[128 * LDA];
    __shared__ __nv_bfloat16 sBl[128 * LDA];

    const int tid = threadIdx.x;
    const int wid = tid >> 5, lane = tid & 31;
    const int g = lane >> 2, t4 = lane & 3;
    const int warp_m = wid >> 2;          // 0..1  (64 rows each)
    const int warp_n = wid & 3;           // 0..3  (32 cols each)
    const int m0 = blockIdx.y * 128, col0 = blockIdx.x * 128;

    // ---- loader mapping: thread t -> (row = t>>1, k-seg = (t&1)*16) ----
    const int rowL = tid >> 1;
    const int ksL  = (tid & 1) * 16;
    const float* Arow = A + (size_t)(m0 + rowL) * KTOT + ksL;

    const int colB = col0 + rowL;
    const int bB = colB / NPIX, pB = colB - bB * NPIX;
    const int hB = pB / 14, wB = pB - hB * 14;
    const float* r5b   = r5 + (size_t)bB * C1 * NPIX;         // conv im2col base
    const float* x1b   = g_x1 + (size_t)bB * 4096 * NPIX + pB;
    const float* tb    = g_t  + (size_t)bB * C1 * NPIX + pB;
    const float* r5col = r5   + (size_t)bB * C1 * NPIX + pB;

    float acc[4][4][4];
#pragma unroll
    for (int i = 0; i < 4; i++)
#pragma unroll
        for (int j = 0; j < 4; j++)
#pragma unroll
            for (int u = 0; u < 4; u++) acc[i][j][u] = 0.f;

    for (int k0 = 0; k0 < KTOT; k0 += 32) {
        // ---- A tile: 16 consecutive fp32, split to bf16 hi/lo ----
        {
            float v[16];
            const float4* p4 = (const float4*)(Arow + k0);
#pragma unroll
            for (int i = 0; i < 4; i++) *(float4*)(v + 4 * i) = p4[i];
#pragma unroll
            for (int i = 0; i < 16; i++)
                split_store(sAh, sAl, rowL * LDA + ksL + i, v[i]);
        }
        // ---- B tile ----
        {
            float v[16];
            if (MODE == 0) {
#pragma unroll 4
                for (int i = 0; i < 16; i++)
                    v[i] = x1b[(size_t)(k0 + ksL + i) * NPIX];
            } else if (MODE == 1) {
                const float* Bp = (k0 + ksL < 2048)
                                      ? (tb + (size_t)(k0 + ksL) * NPIX)
                                      : (r5col + (size_t)(k0 + ksL - 2048) * NPIX);
#pragma unroll 4
                for (int i = 0; i < 16; i++) v[i] = Bp[(size_t)i * NPIX];
            } else {
#pragma unroll 4
                for (int i = 0; i < 16; i++) {
                    int k = k0 + ksL + i;
                    int ci = k / 9, r = k - ci * 9, kh = r / 3, kw = r - kh * 3;
                    int ih = hB + kh - 1, iw = wB + kw - 1;
                    v[i] = ((unsigned)ih < 14u && (unsigned)iw < 14u)
                               ? r5b[(ci * 14 + ih) * 14 + iw] : 0.f;
                }
            }
#pragma unroll
            for (int i = 0; i < 16; i++)
                split_store(sBh, sBl, rowL * LDA + ksL + i, v[i]);
        }
        __syncthreads();

        // ---- 2 k16 steps of 16 frag-MMAs x 3 split terms ----
#pragma unroll
        for (int kk = 0; kk < 32; kk += 16) {
            uint32_t aH[4][4], aL[4][4], bH[4][2], bL[4][2];
#pragma unroll
            for (int fm = 0; fm < 4; fm++) {
                int rb = (warp_m * 64 + fm * 16 + g) * LDA + kk + 2 * t4;
                aH[fm][0] = lds32(sAh, rb);
                aH[fm][1] = lds32(sAh, rb + 8 * LDA);
                aH[fm][2] = lds32(sAh, rb + 8);
                aH[fm][3] = lds32(sAh, rb + 8 * LDA + 8);
                aL[fm][0] = lds32(sAl, rb);
                aL[fm][1] = lds32(sAl, rb + 8 * LDA);
                aL[fm][2] = lds32(sAl, rb + 8);
                aL[fm][3] = lds32(sAl, rb + 8 * LDA + 8);
            }
#pragma unroll
            for (int fn = 0; fn < 4; fn++) {
                int nb = (warp_n * 32 + fn * 8 + g) * LDA + kk + 2 * t4;
                bH[fn][0] = lds32(sBh, nb);
                bH[fn][1] = lds32(sBh, nb + 8);
                bL[fn][0] = lds32(sBl, nb);
                bL[fn][1] = lds32(sBl, nb + 8);
            }
#pragma unroll
            for (int fm = 0; fm < 4; fm++)
#pragma unroll
                for (int fn = 0; fn < 4; fn++) {
                    mma_bf16(acc[fm][fn], aH[fm], bH[fn]);
                    mma_bf16(acc[fm][fn], aH[fm], bL[fn]);
                    mma_bf16(acc[fm][fn], aL[fm], bH[fn]);
                }
        }
        __syncthreads();
    }

    // ---- epilogue ----
    float sc[4][2], sh[4][2];
#pragma unroll
    for (int fm = 0; fm < 4; fm++)
#pragma unroll
        for (int half = 0; half < 2; half++) {
            int m = m0 + warp_m * 64 + fm * 16 + g + half * 8;
            if (MODE == 2) {
                float s = gamma[m] / sqrtf(var[m] + 1e-5f);
                sc[fm][half] = s;
                sh[fm][half] = beta[m] - mean[m] * s;
            } else {
                sc[fm][half] = 1.f;
                sh[fm][half] = bias[m];
            }
        }
#pragma unroll
    for (int fm = 0; fm < 4; fm++) {
#pragma unroll
        for (int fn = 0; fn < 4; fn++) {
#pragma unroll
            for (int u = 0; u < 4; u++) {
                int half = u >> 1;                     // c0,c1 -> rows g; c2,c3 -> g+8
                int m = m0 + warp_m * 64 + fm * 16 + g + half * 8;
                int col = col0 + warp_n * 32 + fn * 8 + 2 * t4 + (u & 1);
                int bo = col / NPIX, n = col - bo * NPIX;
                float vv = acc[fm][fn][u] * sc[fm][half] + sh[fm][half];
                if (MODE == 2) {
                    g_x[((size_t)bo * C2 + m) * NPIX + n] = fmaxf(vv, 0.f);
                } else {
                    size_t oidx = ((size_t)bo * C1 + m) * NPIX + n;
                    if (MODE == 0) g_t[oidx] = r5[oidx] * vv;
                    else           g_xb[oidx] = vv;
                }
            }
        }
    }
}

// ===========================================================================
// Kernel 2: EM attention (stage_num=3), one block per batch
// ===========================================================================
__global__ void __launch_bounds__(256) em_kernel(const float* __restrict__ mu0)
{
    const int b = blockIdx.x;
    const int tid = threadIdx.x, lane = tid & 31, wid = tid >> 5;
    const float* xb = g_x + (size_t)b * C2 * NPIX;

    __shared__ float mu[C2 * 8];
    __shared__ float z[NPIX * 8];
    __shared__ float norm[8], colsum[8];

    {
        float s = 0.f;
        for (int c = lane; c < C2; c += 32) { float v = mu0[c * 8 + wid]; s += v * v; }
#pragma unroll
        for (int o = 16; o; o >>= 1) s += __shfl_xor_sync(0xffffffffu, s, o);
        if (!lane) norm[wid] = sqrtf(s) + EPSF;
    }
    __syncthreads();
    for (int i = tid; i < C2 * 8; i += 256) mu[i] = mu0[i] / norm[i & 7];
    __syncthreads();

    for (int it = 0; it < 3; ++it) {
        if (tid < NPIX) {
            float l[8];
#pragma unroll
            for (int k = 0; k < 8; k++) l[k] = 0.f;
            for (int c = 0; c < C2; c++) {
                float xv = xb[c * NPIX + tid];
#pragma unroll
                for (int k = 0; k < 8; k++) l[k] += xv * mu[c * 8 + k];
            }
            float mx = l[0];
#pragma unroll
            for (int k = 1; k < 8; k++) mx = fmaxf(mx, l[k]);
            float e[8], s = 0.f;
#pragma unroll
            for (int k = 0; k < 8; k++) { e[k] = expf(l[k] - mx); s += e[k]; }
            float inv = 1.f / s;
#pragma unroll
            for (int k = 0; k < 8; k++) z[tid * 8 + k] = e[k] * inv;
        }
        __syncthreads();
        {
            float s = 0.f;
            for (int n = lane; n < NPIX; n += 32) s += z[n * 8 + wid];
#pragma unroll
            for (int o = 16; o; o >>= 1) s += __shfl_xor_sync(0xffffffffu, s, o);
            if (!lane) colsum[wid] = s + EPSF;
        }
        __syncthreads();
        for (int o = tid; o < C2 * 8; o += 256) {
            int c = o >> 3, k = o & 7;
            const float* xr = xb + c * NPIX;
            float s = 0.f;
            for (int n = 0; n < NPIX; n++) s += xr[n] * z[n * 8 + k];
            mu[o] = s / colsum[k];
        }
        __syncthreads();
        {
            float s = 0.f;
            for (int c = lane; c < C2; c += 32) { float v = mu[c * 8 + wid]; s += v * v; }
#pragma unroll
            for (int o = 16; o; o >>= 1) s += __shfl_xor_sync(0xffffffffu, s, o);
            if (!lane) norm[wid] = sqrtf(s) + EPSF;
        }
        __syncthreads();
        for (int i = tid; i < C2 * 8; i += 256) mu[i] /= norm[i & 7];
        __syncthreads();
    }
    if (tid < NPIX) {
        float zr[8];
#pragma unroll
        for (int k = 0; k < 8; k++) zr[k] = z[tid * 8 + k];
        float* x2o = g_x2 + (size_t)b * C2 * NPIX;
        for (int c = 0; c < C2; c++) {
            float s = 0.f;
#pragma unroll
            for (int k = 0; k < 8; k++) s += mu[c * 8 + k] * zr[k];
            float v = xb[c * NPIX + tid] + s;
            x2o[c * NPIX + tid] = fmaxf(v, 0.f);
        }
#pragma unroll
        for (int k = 0; k < 8; k++) g_zt[((size_t)b * 8 + k) * NPIX + tid] = zr[k];
    }
}

// ===========================================================================
// Kernel 3: x1[b, k*512+c, h, v] = sum_w x2[b,c,h,w] * zt[b,k,w,v]
// ===========================================================================
__global__ void __launch_bounds__(256) x1_kernel()
{
    const int b = blockIdx.x, tid = threadIdx.x;
    __shared__ float zts[8 * NPIX];
    for (int i = tid; i < 8 * NPIX; i += 256) zts[i] = g_zt[(size_t)b * 8 * NPIX + i];
    __syncthreads();
    const float* x2b = g_x2 + (size_t)b * C2 * NPIX;
    float* x1b = g_x1 + (size_t)b * 4096 * NPIX;
    for (int r = tid; r < C2 * 14; r += 256) {
        int c = r / 14, h = r - c * 14;
        float xv[14];
        const float* xp = x2b + c * NPIX + h * 14;
#pragma unroll
        for (int w = 0; w < 14; w++) xv[w] = xp[w];
        for (int k = 0; k < 8; k++) {
            float out[14];
#pragma unroll
            for (int v = 0; v < 14; v++) out[v] = 0.f;
#pragma unroll
            for (int w = 0; w < 14; w++) {
                float a = xv[w];
                const float* zp = zts + k * NPIX + w * 14;
#pragma unroll
                for (int v = 0; v < 14; v++) out[v] += a * zp[v];
            }
            float* op = x1b + ((size_t)k * C2 + c) * NPIX + h * 14;
#pragma unroll
            for (int v = 0; v < 14; v++) op[v] = out[v];
        }
    }
}

// ===========================================================================
// Kernel 6: downconv 2048->32 (4 output channels per block)
// ===========================================================================
__global__ void __launch_bounds__(256) down_kernel(
    const float* __restrict__ dw, const float* __restrict__ db)
{
    const int b = blockIdx.x, jg = blockIdx.y, tid = threadIdx.x;
    __shared__ float ws[4 * 2048];
    for (int i = tid; i < 4 * 2048; i += 256) ws[i] = dw[jg * 4 * 2048 + i];
    __syncthreads();
    if (tid < NPIX) {
        float acc[4];
#pragma unroll
        for (int j = 0; j < 4; j++) acc[j] = db[jg * 4 + j];
        const float* xp = g_xb + (size_t)b * C1 * NPIX + tid;
        for (int c = 0; c < 2048; c++) {
            float v = xp[(size_t)c * NPIX];
#pragma unroll
            for (int j = 0; j < 4; j++) acc[j] += ws[j * 2048 + c] * v;
        }
#pragma unroll
        for (int j = 0; j < 4; j++)
            g_xd[((size_t)b * 32 + jg * 4 + j) * NPIX + tid] = acc[j];
    }
}

// ===========================================================================
// Kernel 7: GAP + class-wise pools -> xg (output[0:512]) and xc map
// ===========================================================================
__global__ void __launch_bounds__(256) pool_kernel(float* __restrict__ dout)
{
    const int b = blockIdx.x, tid = threadIdx.x;
    __shared__ float gap[32];
    __shared__ float xgs[8];
    if (tid < 32) {
        const float* p = g_xd + ((size_t)b * 32 + tid) * NPIX;
        float s = 0.f;
        for (int n = 0; n < NPIX; n++) s += p[n];
        gap[tid] = s * (1.f / NPIX);
    }
    __syncthreads();
    if (tid < 8) {
        float g = 0.25f * (gap[4 * tid] + gap[4 * tid + 1] + gap[4 * tid + 2] + gap[4 * tid + 3]);
        xgs[tid] = g;
        dout[b * 8 + tid] = g;
    }
    __syncthreads();
    if (tid < NPIX) {
        const float* p = g_xd + (size_t)b * 32 * NPIX + tid;
        float s = 0.f;
#pragma unroll
        for (int pp = 0; pp < 8; pp++) {
            float cp = 0.25f * (p[(4 * pp + 0) * NPIX] + p[(4 * pp + 1) * NPIX] +
                                p[(4 * pp + 2) * NPIX] + p[(4 * pp + 3) * NPIX]);
            s += cp * xgs[pp];
        }
        g_xc[b * NPIX + tid] = s * 0.125f;
    }
}

// ===========================================================================
// Kernel 8: cls head -> out2 (output[512:1024])
// ===========================================================================
__global__ void __launch_bounds__(256) out2_kernel(
    const float* __restrict__ r5, const float* __restrict__ cw,
    const float* __restrict__ cb, float* __restrict__ dout)
{
    const int b = blockIdx.x, tid = threadIdx.x, lane = tid & 31, wid = tid >> 5;
    __shared__ float xcs[NPIX];
    for (int i = tid; i < NPIX; i += 256) xcs[i] = g_xc[b * NPIX + i];
    __syncthreads();
    const float inv = 1.f / NPIX;
    float accL = 0.f;
    for (int c = wid; c < 2048; c += 8) {
        const float* rp = r5 + ((size_t)b * C1 + c) * NPIX;
        float s1 = 0.f, s2 = 0.f;
        for (int n = lane; n < NPIX; n += 32) { float v = rp[n]; s1 += v; s2 += v * xcs[n]; }
#pragma unroll
        for (int o = 16; o; o >>= 1) {
            s1 += __shfl_xor_sync(0xffffffffu, s1, o);
            s2 += __shfl_xor_sync(0xffffffffu, s2, o);
        }
        if (lane < 8)
            accL += cw[lane * 4096 + c] * s1 * inv + cw[lane * 4096 + 2048 + c] * s2 * inv;
    }
    __shared__ float wsum[8][8];
    if (lane < 8) wsum[wid][lane] = accL;
    __syncthreads();
    if (tid < 8) {
        float s = cb[tid];
#pragma unroll
        for (int w2 = 0; w2 < 8; w2++) s += wsum[w2][tid];
        dout[512 + b * 8 + tid] = s;
    }
}

// ===========================================================================
extern "C" void kernel_launch(void* const* d_in, const int* in_sizes, int n_in,
                              void* d_out, int out_size)
{
    const float* r5   = (const float*)d_in[0];
    const float* fc0  = (const float*)d_in[1];
    const float* bng  = (const float*)d_in[2];
    const float* bnb  = (const float*)d_in[3];
    const float* bnm  = (const float*)d_in[4];
    const float* bnv  = (const float*)d_in[5];
    const float* mu0  = (const float*)d_in[6];
    const float* c4w  = (const float*)d_in[7];
    const float* c4b  = (const float*)d_in[8];
    const float* dw   = (const float*)d_in[9];
    const float* db   = (const float*)d_in[10];
    const float* cw   = (const float*)d_in[11];
    const float* cb   = (const float*)d_in[12];
    float* out = (float*)d_out;

    // conv3x3 + BN + ReLU (M=512)
    mma_gemm_kernel<2><<<dim3(98, 4), 256>>>(fc0, r5, nullptr, bng, bnb, bnm, bnv);
    em_kernel<<<64, 256>>>(mu0);
    x1_kernel<<<64, 256>>>();
    // conv4 pass 1 & 2 (M=2048)
    mma_gemm_kernel<0><<<dim3(98, 16), 256>>>(c4w, r5, c4b, nullptr, nullptr, nullptr, nullptr);
    mma_gemm_kernel<1><<<dim3(98, 16), 256>>>(c4w, r5, c4b, nullptr, nullptr, nullptr, nullptr);
    down_kernel<<<dim3(64, 8), 256>>>(dw, db);
    pool_kernel<<<64, 256>>>(out);
    out2_kernel<<<64, 256>>>(r5, cw, cb, out);
}

// round 5
// speedup vs baseline: 2.0979x; 2.0979x over previous
#include <cuda_runtime.h>
#include <cuda_bf16.h>
#include <cstdint>

#define BATCH 64
#define NPIX  196
#define C1    2048
#define C2    512
#define KCONV 18432
#define K4    4096
#define EPSF  1e-6f

typedef __nv_bfloat16 bf16;

// ---------------- scratch (device globals; no allocation) ----------------
__device__ float g_x [(size_t)BATCH * C2 * NPIX];   // conv+bn+relu output (fp32)
__device__ float g_x2[(size_t)BATCH * C2 * NPIX];   // GCEM output (fp32)
__device__ float g_zt[(size_t)BATCH * 8  * NPIX];   // attention maps (fp32)
__device__ float g_xb[(size_t)BATCH * C1 * NPIX];   // conv4(concat) output (fp32)
__device__ float g_xd[(size_t)BATCH * 32 * NPIX];   // downconv (fp32)
__device__ float g_xc[(size_t)BATCH * NPIX];        // pooled attention map (fp32)

// bf16 hi/lo split operands
__device__ __align__(128) bf16 g_fcH [(size_t)C2 * KCONV];
__device__ __align__(128) bf16 g_fcL [(size_t)C2 * KCONV];
__device__ __align__(128) bf16 g_c4H [(size_t)C1 * K4];
__device__ __align__(128) bf16 g_c4L [(size_t)C1 * K4];
__device__ __align__(128) bf16 g_r5TH[(size_t)BATCH * NPIX * C1];   // [b*196+n][c]
__device__ __align__(128) bf16 g_r5TL[(size_t)BATCH * NPIX * C1];
__device__ __align__(128) bf16 g_imH [(size_t)BATCH * NPIX * KCONV]; // im2col [col][k]
__device__ __align__(128) bf16 g_imL [(size_t)BATCH * NPIX * KCONV];
__device__ __align__(128) bf16 g_x1TH[(size_t)BATCH * NPIX * K4];   // [col][kc]
__device__ __align__(128) bf16 g_x1TL[(size_t)BATCH * NPIX * K4];
__device__ __align__(128) bf16 g_tTH [(size_t)BATCH * NPIX * C1];   // [col][c]
__device__ __align__(128) bf16 g_tTL [(size_t)BATCH * NPIX * C1];

// ===========================================================================
// helpers
// ===========================================================================
__device__ __forceinline__ void mma_bf16(float* d, const uint32_t* a, const uint32_t* b)
{
    asm volatile(
        "mma.sync.aligned.m16n8k16.row.col.f32.bf16.bf16.f32 "
        "{%0,%1,%2,%3}, {%4,%5,%6,%7}, {%8,%9}, {%0,%1,%2,%3};"
        : "+f"(d[0]), "+f"(d[1]), "+f"(d[2]), "+f"(d[3])
        : "r"(a[0]), "r"(a[1]), "r"(a[2]), "r"(a[3]), "r"(b[0]), "r"(b[1]));
}
__device__ __forceinline__ uint32_t lds32(const bf16* base, int elem)
{
    return *(const uint32_t*)(base + elem);
}
__device__ __forceinline__ void fsplit(float v, bf16& h, bf16& l)
{
    h = __float2bfloat16(v);
    l = __float2bfloat16(v - __bfloat162float(h));
}
__device__ __forceinline__ uint32_t smem_u32(const void* p) {
    uint32_t a;
    asm("{ .reg .u64 t; cvta.to.shared.u64 t, %1; cvt.u32.u64 %0, t; }" : "=r"(a) : "l"(p));
    return a;
}
__device__ __forceinline__ void cpa16(uint32_t dst, const void* src) {
    asm volatile("cp.async.cg.shared.global [%0], [%1], 16;" :: "r"(dst), "l"(src));
}
__device__ __forceinline__ void cpa_commit() {
    asm volatile("cp.async.commit_group;" ::: "memory");
}

// ===========================================================================
// prep: generic fp32 -> bf16 hi/lo split
// ===========================================================================
__global__ void cvt_split_kernel(const float* __restrict__ src, bf16* __restrict__ h,
                                 bf16* __restrict__ l, size_t n)
{
    for (size_t i = (size_t)blockIdx.x * blockDim.x + threadIdx.x; i < n;
         i += (size_t)gridDim.x * blockDim.x) {
        bf16 hh, ll;
        fsplit(src[i], hh, ll);
        h[i] = hh; l[i] = ll;
    }
}

// prep: r5 [b][c][n] -> r5T hi/lo [(b*196+n)][c]
__global__ void r5T_kernel(const float* __restrict__ r5)
{
    __shared__ float tile[32][33];
    const int b = blockIdx.x, c0 = blockIdx.y * 32, n0 = blockIdx.z * 32;
    const int tx = threadIdx.x, ty = threadIdx.y;   // 32 x 8
#pragma unroll
    for (int j = 0; j < 4; j++) {
        int c = c0 + ty + j * 8, n = n0 + tx;
        if (n < NPIX) tile[ty + j * 8][tx] = r5[((size_t)b * C1 + c) * NPIX + n];
    }
    __syncthreads();
#pragma unroll
    for (int j = 0; j < 4; j++) {
        int n = n0 + ty + j * 8, c = c0 + tx;
        if (n < NPIX) {
            bf16 hh, ll;
            fsplit(tile[tx][ty + j * 8], hh, ll);
            size_t o = ((size_t)b * NPIX + n) * C1 + c;
            g_r5TH[o] = hh; g_r5TL[o] = ll;
        }
    }
}

// prep: im2col of r5 -> g_im hi/lo [(b*196+n)][k], k = ci*9+kh*3+kw
__global__ void __launch_bounds__(256) im2col_kernel(const float* __restrict__ r5)
{
    const int b = blockIdx.x;
    const int wid = threadIdx.x >> 5, lane = threadIdx.x & 31;
    const int n = blockIdx.y * 8 + wid;
    if (n >= NPIX) return;
    const int h = n / 14, w = n - h * 14;
    const float* r5b = r5 + (size_t)b * C1 * NPIX;
    bf16* oh = g_imH + ((size_t)b * NPIX + n) * KCONV;
    bf16* ol = g_imL + ((size_t)b * NPIX + n) * KCONV;
    for (int k = lane; k < KCONV; k += 32) {
        int ci = k / 9, r = k - ci * 9, kh = r / 3, kw = r - kh * 3;
        int ih = h + kh - 1, iw = w + kw - 1;
        float v = ((unsigned)ih < 14u && (unsigned)iw < 14u)
                      ? r5b[(ci * 14 + ih) * 14 + iw] : 0.f;
        bf16 hh, ll;
        fsplit(v, hh, ll);
        oh[k] = hh; ol[k] = ll;
    }
}

// ===========================================================================
// Unified tensor-core GEMM: block 128x128, chunk 32, 2-stage cp.async pipeline
// MODE 0: A=c4w,  B=x1T,        out tT = r5*(acc+bias)     (bf16 split)
// MODE 1: A=c4w,  B=[tT;r5T],   out g_xb = acc+bias        (fp32)
// MODE 2: A=fc0w, B=im2col(r5), out g_x = relu(BN(acc))    (fp32)
// ===========================================================================
#define SROW 40
#define MATE (128 * SROW)     // 5120 elems per matrix tile
#define STGE (4 * MATE)       // 20480 elems per stage
#define STGB (STGE * 2)       // 40960 bytes per stage
#define SM_BYTES (2 * STGB)   // 81920

template <int MODE>
__global__ void __launch_bounds__(256, 1) mma_gemm_kernel(
    const bf16* __restrict__ Ah, const bf16* __restrict__ Al,
    const float* __restrict__ r5, const float* __restrict__ bias,
    const float* __restrict__ gamma, const float* __restrict__ beta,
    const float* __restrict__ mean,  const float* __restrict__ var)
{
    constexpr int KTOT = (MODE == 2) ? KCONV : K4;
    constexpr int NC = KTOT / 32;

    extern __shared__ bf16 sm[];
    const uint32_t sb = smem_u32(sm);

    const int tid = threadIdx.x;
    const int wid = tid >> 5, lane = tid & 31;
    const int g = lane >> 2, t4 = lane & 3;
    const int warp_m = wid >> 2, warp_n = wid & 3;
    const int m0 = blockIdx.y * 128, col0 = blockIdx.x * 128;

    // loader mapping: thread -> (row = tid>>1, half = tid&1) ; 32B per half
    const int rowL = tid >> 1;
    const int half = tid & 1;
    const size_t aOfs = (size_t)(m0 + rowL) * KTOT + half * 16;
    const int colL = col0 + rowL;

    const bf16 *bH0, *bL0;          // B row base (k-contiguous)
    if (MODE == 0) {
        bH0 = g_x1TH + (size_t)colL * K4 + half * 16;
        bL0 = g_x1TL + (size_t)colL * K4 + half * 16;
    } else if (MODE == 2) {
        bH0 = g_imH + (size_t)colL * KCONV + half * 16;
        bL0 = g_imL + (size_t)colL * KCONV + half * 16;
    } else {
        bH0 = g_tTH + (size_t)colL * C1 + half * 16;   // k<2048 part
        bL0 = g_tTL + (size_t)colL * C1 + half * 16;
    }
    const bf16* bH1 = g_r5TH + (size_t)colL * C1 + half * 16;  // MODE1 k>=2048
    const bf16* bL1 = g_r5TL + (size_t)colL * C1 + half * 16;

    const uint32_t dBase = sb + rowL * (SROW * 2) + half * 32;

    // ---- stage loader ----
    auto load_stage = [&](int st, int k0) {
        uint32_t d = dBase + st * STGB;
        const bf16* aph = Ah + aOfs + k0;
        const bf16* apl = Al + aOfs + k0;
        const bf16 *bph, *bpl;
        if (MODE == 1 && k0 >= 2048) { bph = bH1 + (k0 - 2048); bpl = bL1 + (k0 - 2048); }
        else                         { bph = bH0 + k0;          bpl = bL0 + k0; }
        cpa16(d,                    aph);     cpa16(d + 16,                aph + 8);
        cpa16(d + MATE * 2,         apl);     cpa16(d + MATE * 2 + 16,     apl + 8);
        cpa16(d + MATE * 4,         bph);     cpa16(d + MATE * 4 + 16,     bph + 8);
        cpa16(d + MATE * 6,         bpl);     cpa16(d + MATE * 6 + 16,     bpl + 8);
        cpa_commit();
    };

    float acc[4][4][4];
#pragma unroll
    for (int i = 0; i < 4; i++)
#pragma unroll
        for (int j = 0; j < 4; j++)
#pragma unroll
            for (int u = 0; u < 4; u++) acc[i][j][u] = 0.f;

    load_stage(0, 0);

    for (int c = 0; c < NC; c++) {
        if (c + 1 < NC) {
            load_stage((c + 1) & 1, (c + 1) * 32);
            asm volatile("cp.async.wait_group 1;" ::: "memory");
        } else {
            asm volatile("cp.async.wait_group 0;" ::: "memory");
        }
        __syncthreads();

        const bf16* pAh = sm + (size_t)(c & 1) * STGE;
        const bf16* pAl = pAh + MATE;
        const bf16* pBh = pAh + 2 * MATE;
        const bf16* pBl = pAh + 3 * MATE;

#pragma unroll
        for (int kk = 0; kk < 32; kk += 16) {
            uint32_t aH[4][4], aL[4][4], bH[4][2], bL[4][2];
#pragma unroll
            for (int fm = 0; fm < 4; fm++) {
                int rb = (warp_m * 64 + fm * 16 + g) * SROW + kk + 2 * t4;
                aH[fm][0] = lds32(pAh, rb);
                aH[fm][1] = lds32(pAh, rb + 8 * SROW);
                aH[fm][2] = lds32(pAh, rb + 8);
                aH[fm][3] = lds32(pAh, rb + 8 * SROW + 8);
                aL[fm][0] = lds32(pAl, rb);
                aL[fm][1] = lds32(pAl, rb + 8 * SROW);
                aL[fm][2] = lds32(pAl, rb + 8);
                aL[fm][3] = lds32(pAl, rb + 8 * SROW + 8);
            }
#pragma unroll
            for (int fn = 0; fn < 4; fn++) {
                int nb = (warp_n * 32 + fn * 8 + g) * SROW + kk + 2 * t4;
                bH[fn][0] = lds32(pBh, nb);
                bH[fn][1] = lds32(pBh, nb + 8);
                bL[fn][0] = lds32(pBl, nb);
                bL[fn][1] = lds32(pBl, nb + 8);
            }
#pragma unroll
            for (int fm = 0; fm < 4; fm++)
#pragma unroll
                for (int fn = 0; fn < 4; fn++) {
                    mma_bf16(acc[fm][fn], aH[fm], bH[fn]);
                    mma_bf16(acc[fm][fn], aH[fm], bL[fn]);
                    mma_bf16(acc[fm][fn], aL[fm], bH[fn]);
                }
        }
        __syncthreads();
    }

    // ---- epilogue ----
    float sc[4][2], sh[4][2];
#pragma unroll
    for (int fm = 0; fm < 4; fm++)
#pragma unroll
        for (int hf = 0; hf < 2; hf++) {
            int m = m0 + warp_m * 64 + fm * 16 + g + hf * 8;
            if (MODE == 2) {
                float s = gamma[m] / sqrtf(var[m] + 1e-5f);
                sc[fm][hf] = s;
                sh[fm][hf] = beta[m] - mean[m] * s;
            } else {
                sc[fm][hf] = 1.f;
                sh[fm][hf] = bias[m];
            }
        }
#pragma unroll
    for (int fm = 0; fm < 4; fm++) {
#pragma unroll
        for (int fn = 0; fn < 4; fn++) {
#pragma unroll
            for (int u = 0; u < 4; u++) {
                int hf = u >> 1;
                int m = m0 + warp_m * 64 + fm * 16 + g + hf * 8;
                int col = col0 + warp_n * 32 + fn * 8 + 2 * t4 + (u & 1);
                int bo = col / NPIX, n = col - bo * NPIX;
                float vv = acc[fm][fn][u] * sc[fm][hf] + sh[fm][hf];
                if (MODE == 2) {
                    g_x[((size_t)bo * C2 + m) * NPIX + n] = fmaxf(vv, 0.f);
                } else if (MODE == 1) {
                    g_xb[((size_t)bo * C1 + m) * NPIX + n] = vv;
                } else {
                    float tv = r5[((size_t)bo * C1 + m) * NPIX + n] * vv;
                    bf16 hh, ll;
                    fsplit(tv, hh, ll);
                    size_t o = (size_t)col * C1 + m;
                    g_tTH[o] = hh; g_tTL[o] = ll;
                }
            }
        }
    }
}

// ===========================================================================
// EM attention (stage_num=3), one block per batch
// ===========================================================================
__global__ void __launch_bounds__(256) em_kernel(const float* __restrict__ mu0)
{
    const int b = blockIdx.x;
    const int tid = threadIdx.x, lane = tid & 31, wid = tid >> 5;
    const float* xb = g_x + (size_t)b * C2 * NPIX;

    __shared__ float mu[C2 * 8];
    __shared__ float z[NPIX * 8];
    __shared__ float norm[8], colsum[8];

    {
        float s = 0.f;
        for (int c = lane; c < C2; c += 32) { float v = mu0[c * 8 + wid]; s += v * v; }
#pragma unroll
        for (int o = 16; o; o >>= 1) s += __shfl_xor_sync(0xffffffffu, s, o);
        if (!lane) norm[wid] = sqrtf(s) + EPSF;
    }
    __syncthreads();
    for (int i = tid; i < C2 * 8; i += 256) mu[i] = mu0[i] / norm[i & 7];
    __syncthreads();

    for (int it = 0; it < 3; ++it) {
        if (tid < NPIX) {
            float l[8];
#pragma unroll
            for (int k = 0; k < 8; k++) l[k] = 0.f;
            for (int c = 0; c < C2; c++) {
                float xv = xb[c * NPIX + tid];
#pragma unroll
                for (int k = 0; k < 8; k++) l[k] += xv * mu[c * 8 + k];
            }
            float mx = l[0];
#pragma unroll
            for (int k = 1; k < 8; k++) mx = fmaxf(mx, l[k]);
            float e[8], s = 0.f;
#pragma unroll
            for (int k = 0; k < 8; k++) { e[k] = expf(l[k] - mx); s += e[k]; }
            float inv = 1.f / s;
#pragma unroll
            for (int k = 0; k < 8; k++) z[tid * 8 + k] = e[k] * inv;
        }
        __syncthreads();
        {
            float s = 0.f;
            for (int n = lane; n < NPIX; n += 32) s += z[n * 8 + wid];
#pragma unroll
            for (int o = 16; o; o >>= 1) s += __shfl_xor_sync(0xffffffffu, s, o);
            if (!lane) colsum[wid] = s + EPSF;
        }
        __syncthreads();
        for (int o = tid; o < C2 * 8; o += 256) {
            int c = o >> 3, k = o & 7;
            const float* xr = xb + c * NPIX;
            float s = 0.f;
            for (int n = 0; n < NPIX; n++) s += xr[n] * z[n * 8 + k];
            mu[o] = s / colsum[k];
        }
        __syncthreads();
        {
            float s = 0.f;
            for (int c = lane; c < C2; c += 32) { float v = mu[c * 8 + wid]; s += v * v; }
#pragma unroll
            for (int o = 16; o; o >>= 1) s += __shfl_xor_sync(0xffffffffu, s, o);
            if (!lane) norm[wid] = sqrtf(s) + EPSF;
        }
        __syncthreads();
        for (int i = tid; i < C2 * 8; i += 256) mu[i] /= norm[i & 7];
        __syncthreads();
    }
    if (tid < NPIX) {
        float zr[8];
#pragma unroll
        for (int k = 0; k < 8; k++) zr[k] = z[tid * 8 + k];
        float* x2o = g_x2 + (size_t)b * C2 * NPIX;
        for (int c = 0; c < C2; c++) {
            float s = 0.f;
#pragma unroll
            for (int k = 0; k < 8; k++) s += mu[c * 8 + k] * zr[k];
            float v = xb[c * NPIX + tid] + s;
            x2o[c * NPIX + tid] = fmaxf(v, 0.f);
        }
#pragma unroll
        for (int k = 0; k < 8; k++) g_zt[((size_t)b * 8 + k) * NPIX + tid] = zr[k];
    }
}

// ===========================================================================
// x1T: x1T[(b*196+h*14+v)][k*512+c] = sum_w x2[b,c,h*14+w] * zt[b,k,w*14+v]
// (written directly as bf16 hi/lo split, k-contiguous rows; block per (b,h))
// ===========================================================================
__global__ void __launch_bounds__(256) x1T_kernel()
{
    const int b = blockIdx.x, h = blockIdx.y;
    const int tid = threadIdx.x, lane = tid & 31, wid = tid >> 5;

    __shared__ float x2s[C2 * 14];      // x2[c][w] slice for this h
    __shared__ float zts[8 * NPIX];
    for (int i = tid; i < C2 * 14; i += 256) {
        int c = i / 14, w = i - c * 14;
        x2s[i] = g_x2[((size_t)b * C2 + c) * NPIX + h * 14 + w];
    }
    for (int i = tid; i < 8 * NPIX; i += 256) zts[i] = g_zt[(size_t)b * 8 * NPIX + i];
    __syncthreads();

    // 8 warps x 2 iters cover 512 channels; lanes = consecutive c
    for (int ci = 0; ci < 2; ci++) {
        const int c = wid * 64 + ci * 32 + lane;
        float xv[14];
#pragma unroll
        for (int w = 0; w < 14; w++) xv[w] = x2s[c * 14 + w];
#pragma unroll
        for (int k = 0; k < 8; k++) {
            float out[14];
#pragma unroll
            for (int v = 0; v < 14; v++) out[v] = 0.f;
#pragma unroll
            for (int w = 0; w < 14; w++) {
                float a = xv[w];
                const float* zp = zts + k * NPIX + w * 14;
#pragma unroll
                for (int v = 0; v < 14; v++) out[v] += a * zp[v];
            }
#pragma unroll
            for (int v = 0; v < 14; v++) {
                bf16 hh, ll;
                fsplit(out[v], hh, ll);
                size_t o = ((size_t)b * NPIX + h * 14 + v) * K4 + k * C2 + c;
                g_x1TH[o] = hh; g_x1TL[o] = ll;
            }
        }
    }
}

// ===========================================================================
// downconv 2048->32 (4 output channels per block)
// ===========================================================================
__global__ void __launch_bounds__(256) down_kernel(
    const float* __restrict__ dw, const float* __restrict__ db)
{
    const int b = blockIdx.x, jg = blockIdx.y, tid = threadIdx.x;
    __shared__ float ws[4 * 2048];
    for (int i = tid; i < 4 * 2048; i += 256) ws[i] = dw[jg * 4 * 2048 + i];
    __syncthreads();
    if (tid < NPIX) {
        float acc[4];
#pragma unroll
        for (int j = 0; j < 4; j++) acc[j] = db[jg * 4 + j];
        const float* xp = g_xb + (size_t)b * C1 * NPIX + tid;
        for (int c = 0; c < 2048; c++) {
            float v = xp[(size_t)c * NPIX];
#pragma unroll
            for (int j = 0; j < 4; j++) acc[j] += ws[j * 2048 + c] * v;
        }
#pragma unroll
        for (int j = 0; j < 4; j++)
            g_xd[((size_t)b * 32 + jg * 4 + j) * NPIX + tid] = acc[j];
    }
}

// ===========================================================================
// GAP + class-wise pools -> xg (output[0:512]) and xc map
// ===========================================================================
__global__ void __launch_bounds__(256) pool_kernel(float* __restrict__ dout)
{
    const int b = blockIdx.x, tid = threadIdx.x;
    __shared__ float gap[32];
    __shared__ float xgs[8];
    if (tid < 32) {
        const float* p = g_xd + ((size_t)b * 32 + tid) * NPIX;
        float s = 0.f;
        for (int n = 0; n < NPIX; n++) s += p[n];
        gap[tid] = s * (1.f / NPIX);
    }
    __syncthreads();
    if (tid < 8) {
        float g = 0.25f * (gap[4 * tid] + gap[4 * tid + 1] + gap[4 * tid + 2] + gap[4 * tid + 3]);
        xgs[tid] = g;
        dout[b * 8 + tid] = g;
    }
    __syncthreads();
    if (tid < NPIX) {
        const float* p = g_xd + (size_t)b * 32 * NPIX + tid;
        float s = 0.f;
#pragma unroll
        for (int pp = 0; pp < 8; pp++) {
            float cp = 0.25f * (p[(4 * pp + 0) * NPIX] + p[(4 * pp + 1) * NPIX] +
                                p[(4 * pp + 2) * NPIX] + p[(4 * pp + 3) * NPIX]);
            s += cp * xgs[pp];
        }
        g_xc[b * NPIX + tid] = s * 0.125f;
    }
}

// ===========================================================================
// cls head -> out2 (output[512:1024])
// ===========================================================================
__global__ void __launch_bounds__(256) out2_kernel(
    const float* __restrict__ r5, const float* __restrict__ cw,
    const float* __restrict__ cb, float* __restrict__ dout)
{
    const int b = blockIdx.x, tid = threadIdx.x, lane = tid & 31, wid = tid >> 5;
    __shared__ float xcs[NPIX];
    for (int i = tid; i < NPIX; i += 256) xcs[i] = g_xc[b * NPIX + i];
    __syncthreads();
    const float inv = 1.f / NPIX;
    float accL = 0.f;
    for (int c = wid; c < 2048; c += 8) {
        const float* rp = r5 + ((size_t)b * C1 + c) * NPIX;
        float s1 = 0.f, s2 = 0.f;
        for (int n = lane; n < NPIX; n += 32) { float v = rp[n]; s1 += v; s2 += v * xcs[n]; }
#pragma unroll
        for (int o = 16; o; o >>= 1) {
            s1 += __shfl_xor_sync(0xffffffffu, s1, o);
            s2 += __shfl_xor_sync(0xffffffffu, s2, o);
        }
        if (lane < 8)
            accL += cw[lane * 4096 + c] * s1 * inv + cw[lane * 4096 + 2048 + c] * s2 * inv;
    }
    __shared__ float wsum[8][8];
    if (lane < 8) wsum[wid][lane] = accL;
    __syncthreads();
    if (tid < 8) {
        float s = cb[tid];
#pragma unroll
        for (int w2 = 0; w2 < 8; w2++) s += wsum[w2][tid];
        dout[512 + b * 8 + tid] = s;
    }
}

// ===========================================================================
extern "C" void kernel_launch(void* const* d_in, const int* in_sizes, int n_in,
                              void* d_out, int out_size)
{
    const float* r5   = (const float*)d_in[0];
    const float* fc0  = (const float*)d_in[1];
    const float* bng  = (const float*)d_in[2];
    const float* bnb  = (const float*)d_in[3];
    const float* bnm  = (const float*)d_in[4];
    const float* bnv  = (const float*)d_in[5];
    const float* mu0  = (const float*)d_in[6];
    const float* c4w  = (const float*)d_in[7];
    const float* c4b  = (const float*)d_in[8];
    const float* dw   = (const float*)d_in[9];
    const float* db   = (const float*)d_in[10];
    const float* cw   = (const float*)d_in[11];
    const float* cb   = (const float*)d_in[12];
    float* out = (float*)d_out;

    static int smem_set = 0;
    if (!smem_set) {
        cudaFuncSetAttribute(mma_gemm_kernel<0>, cudaFuncAttributeMaxDynamicSharedMemorySize, SM_BYTES);
        cudaFuncSetAttribute(mma_gemm_kernel<1>, cudaFuncAttributeMaxDynamicSharedMemorySize, SM_BYTES);
        cudaFuncSetAttribute(mma_gemm_kernel<2>, cudaFuncAttributeMaxDynamicSharedMemorySize, SM_BYTES);
        smem_set = 1;
    }

    bf16 *fcH, *fcL, *c4H, *c4L;
    cudaGetSymbolAddress((void**)&fcH, g_fcH);
    cudaGetSymbolAddress((void**)&fcL, g_fcL);
    cudaGetSymbolAddress((void**)&c4H, g_c4H);
    cudaGetSymbolAddress((void**)&c4L, g_c4L);

    // ---- prep: split weights + activations ----
    cvt_split_kernel<<<2048, 256>>>(fc0, fcH, fcL, (size_t)C2 * KCONV);
    cvt_split_kernel<<<2048, 256>>>(c4w, c4H, c4L, (size_t)C1 * K4);
    r5T_kernel<<<dim3(64, 64, 7), dim3(32, 8)>>>(r5);
    im2col_kernel<<<dim3(64, 25), 256>>>(r5);

    // ---- conv3x3 + BN + ReLU ----
    mma_gemm_kernel<2><<<dim3(98, 4), 256, SM_BYTES>>>(fcH, fcL, r5, nullptr, bng, bnb, bnm, bnv);
    em_kernel<<<64, 256>>>(mu0);
    x1T_kernel<<<dim3(64, 14), 256>>>();
    // ---- conv4 pass 1 & 2 ----
    mma_gemm_kernel<0><<<dim3(98, 16), 256, SM_BYTES>>>(c4H, c4L, r5, c4b, nullptr, nullptr, nullptr, nullptr);
    mma_gemm_kernel<1><<<dim3(98, 16), 256, SM_BYTES>>>(c4H, c4L, r5, c4b, nullptr, nullptr, nullptr, nullptr);
    down_kernel<<<dim3(64, 8), 256>>>(dw, db);
    pool_kernel<<<64, 256>>>(out);
    out2_kernel<<<64, 256>>>(r5, cw, cb, out);
}

// round 7
// speedup vs baseline: 2.1687x; 1.0337x over previous
#include <cuda_runtime.h>
#include <cuda_bf16.h>
#include <cstdint>

#define BATCH 64
#define NPIX  196
#define C1    2048
#define C2    512
#define KCONV 18432
#define K4    4096
#define EPSF  1e-6f

typedef __nv_bfloat16 bf16;

// ---------------- scratch (device globals; no allocation) ----------------
__device__ float g_x [(size_t)BATCH * C2 * NPIX];   // conv+bn+relu output (fp32)
__device__ float g_x2[(size_t)BATCH * C2 * NPIX];   // GCEM output (fp32)
__device__ float g_zt[(size_t)BATCH * 8  * NPIX];   // attention maps (fp32)
__device__ float g_xb[(size_t)BATCH * C1 * NPIX];   // conv4(concat) output (fp32)
__device__ float g_xd[(size_t)BATCH * 32 * NPIX];   // downconv (fp32)
__device__ float g_xc[(size_t)BATCH * NPIX];        // pooled attention map (fp32)

// bf16 hi/lo split operands
__device__ __align__(128) bf16 g_fcH [(size_t)C2 * KCONV];   // fc0 permuted: k=(kh*3+kw)*2048+ci
__device__ __align__(128) bf16 g_fcL [(size_t)C2 * KCONV];
__device__ __align__(128) bf16 g_c4H [(size_t)C1 * K4];
__device__ __align__(128) bf16 g_c4L [(size_t)C1 * K4];
__device__ __align__(128) bf16 g_r5PH[(size_t)BATCH * 256 * C1];  // padded transpose [b][16][16][c]
__device__ __align__(128) bf16 g_r5PL[(size_t)BATCH * 256 * C1];
__device__ __align__(128) bf16 g_x1TH[(size_t)BATCH * NPIX * K4]; // [col][kc]
__device__ __align__(128) bf16 g_x1TL[(size_t)BATCH * NPIX * K4];
__device__ __align__(128) bf16 g_tTH [(size_t)BATCH * NPIX * C1]; // [col][c]
__device__ __align__(128) bf16 g_tTL [(size_t)BATCH * NPIX * C1];

// ===========================================================================
// helpers
// ===========================================================================
__device__ __forceinline__ void mma_bf16(float* d, const uint32_t* a, const uint32_t* b)
{
    asm volatile(
        "mma.sync.aligned.m16n8k16.row.col.f32.bf16.bf16.f32 "
        "{%0,%1,%2,%3}, {%4,%5,%6,%7}, {%8,%9}, {%0,%1,%2,%3};"
        : "+f"(d[0]), "+f"(d[1]), "+f"(d[2]), "+f"(d[3])
        : "r"(a[0]), "r"(a[1]), "r"(a[2]), "r"(a[3]), "r"(b[0]), "r"(b[1]));
}
__device__ __forceinline__ uint32_t lds32(const bf16* base, int elem)
{
    return *(const uint32_t*)(base + elem);
}
__device__ __forceinline__ void fsplit(float v, bf16& h, bf16& l)
{
    h = __float2bfloat16(v);
    l = __float2bfloat16(v - __bfloat162float(h));
}
__device__ __forceinline__ uint32_t smem_u32(const void* p) {
    uint32_t a;
    asm("{ .reg .u64 t; cvta.to.shared.u64 t, %1; cvt.u32.u64 %0, t; }" : "=r"(a) : "l"(p));
    return a;
}
__device__ __forceinline__ void cpa16(uint32_t dst, const void* src) {
    asm volatile("cp.async.cg.shared.global [%0], [%1], 16;" :: "r"(dst), "l"(src));
}
__device__ __forceinline__ void cpa_commit() {
    asm volatile("cp.async.commit_group;" ::: "memory");
}

// ===========================================================================
// prep kernels
// ===========================================================================
__global__ void cvt_split_kernel(const float* __restrict__ src, bf16* __restrict__ h,
                                 bf16* __restrict__ l, size_t n)
{
    for (size_t i = (size_t)blockIdx.x * blockDim.x + threadIdx.x; i < n;
         i += (size_t)gridDim.x * blockDim.x) {
        bf16 hh, ll;
        fsplit(src[i], hh, ll);
        h[i] = hh; l[i] = ll;
    }
}

// fc0 [m][ci*9 + kh*3 + kw] -> g_fc [m][(kh*3+kw)*2048 + ci] (split)
__global__ void fc0_perm_kernel(const float* __restrict__ src)
{
    for (size_t i = (size_t)blockIdx.x * blockDim.x + threadIdx.x;
         i < (size_t)C2 * KCONV; i += (size_t)gridDim.x * blockDim.x) {
        size_t m = i / KCONV;
        int kk = (int)(i - m * KCONV);
        int s = kk >> 11, ci = kk & 2047;
        bf16 hh, ll;
        fsplit(src[m * KCONV + (size_t)ci * 9 + s], hh, ll);
        g_fcH[i] = hh; g_fcL[i] = ll;
    }
}

// zero-fill padded r5P (both hi and lo), uint2 = 4 bf16 per store
__global__ void r5P_zero_kernel()
{
    size_t n4 = (size_t)BATCH * 256 * C1 / 4;
    uint2 z = make_uint2(0u, 0u);
    uint2* ph = (uint2*)g_r5PH;
    uint2* pl = (uint2*)g_r5PL;
    for (size_t i = (size_t)blockIdx.x * blockDim.x + threadIdx.x; i < n4;
         i += (size_t)gridDim.x * blockDim.x) {
        ph[i] = z; pl[i] = z;
    }
}

// interior fill: r5 [b][c][n] -> r5P [b][h+1][w+1][c] (transpose via smem tile)
__global__ void r5P_fill_kernel(const float* __restrict__ r5)
{
    __shared__ float tile[32][33];
    const int b = blockIdx.x, c0 = blockIdx.y * 32, n0 = blockIdx.z * 32;
    const int tx = threadIdx.x, ty = threadIdx.y;   // 32 x 8
#pragma unroll
    for (int j = 0; j < 4; j++) {
        int c = c0 + ty + j * 8, n = n0 + tx;
        if (n < NPIX) tile[ty + j * 8][tx] = r5[((size_t)b * C1 + c) * NPIX + n];
    }
    __syncthreads();
#pragma unroll
    for (int j = 0; j < 4; j++) {
        int n = n0 + ty + j * 8, c = c0 + tx;
        if (n < NPIX) {
            int h = n / 14, w = n - h * 14;
            bf16 hh, ll;
            fsplit(tile[tx][ty + j * 8], hh, ll);
            size_t o = (((size_t)b * 16 + h + 1) * 16 + (w + 1)) * C1 + c;
            g_r5PH[o] = hh; g_r5PL[o] = ll;
        }
    }
}

// ===========================================================================
// Unified tensor-core GEMM: block 128x128, chunk 32, 2-stage cp.async pipeline
// MODE 0: A=c4w,  B=x1T,             out tT = r5*(acc+bias)  (bf16 split)
// MODE 1: A=c4w,  B=[tT;r5P-center], out g_xb = acc+bias     (fp32)
// MODE 2: A=fc0P, B=shifted r5P,     out g_x = relu(BN(acc)) (fp32)
// ===========================================================================
#define SROW 40
#define MATE (128 * SROW)     // 5120 elems per matrix tile
#define STGE (4 * MATE)       // 20480 elems per stage
#define STGB (STGE * 2)       // 40960 bytes per stage
#define SM_BYTES (2 * STGB)   // 81920

template <int MODE>
__global__ void __launch_bounds__(256, 1) mma_gemm_kernel(
    const bf16* __restrict__ Ah, const bf16* __restrict__ Al,
    const float* __restrict__ r5, const float* __restrict__ bias,
    const float* __restrict__ gamma, const float* __restrict__ beta,
    const float* __restrict__ mean,  const float* __restrict__ var)
{
    constexpr int KTOT = (MODE == 2) ? KCONV : K4;
    constexpr int NC = KTOT / 32;

    extern __shared__ bf16 sm[];
    const uint32_t sb = smem_u32(sm);

    const int tid = threadIdx.x;
    const int wid = tid >> 5, lane = tid & 31;
    const int g = lane >> 2, t4 = lane & 3;
    const int warp_m = wid >> 2, warp_n = wid & 3;
    const int m0 = blockIdx.y * 128, col0 = blockIdx.x * 128;

    // loader mapping: thread -> (row = tid>>1, half = tid&1) ; 32B per half
    const int rowL = tid >> 1;
    const int half = tid & 1;
    const size_t aOfs = (size_t)(m0 + rowL) * KTOT + half * 16;
    const int colL = col0 + rowL;
    const int bB = colL / NPIX, pB = colL - bB * NPIX;
    const int hB = pB / 14, wB = pB - hB * 14;

    // B base pointers
    const bf16 *bH0, *bL0;
    if (MODE == 0) {
        bH0 = g_x1TH + (size_t)colL * K4 + half * 16;
        bL0 = g_x1TL + (size_t)colL * K4 + half * 16;
    } else {
        bH0 = g_tTH + (size_t)colL * C1 + half * 16;      // MODE1 k<2048 part
        bL0 = g_tTL + (size_t)colL * C1 + half * 16;
    }
    // padded r5P cell base for (b, hB, wB); shift (kh,kw) adds (kh*16+kw)*C1
    const size_t padBase = (((size_t)bB * 16 + hB) * 16 + wB) * C1 + half * 16;
    const bf16* pPH = g_r5PH + padBase;
    const bf16* pPL = g_r5PL + padBase;

    const uint32_t dBase = sb + rowL * (SROW * 2) + half * 32;

    auto load_stage = [&](int st, int k0) {
        uint32_t d = dBase + st * STGB;
        const bf16* aph = Ah + aOfs + k0;
        const bf16* apl = Al + aOfs + k0;
        const bf16 *bph, *bpl;
        if (MODE == 0) {
            bph = bH0 + k0; bpl = bL0 + k0;
        } else if (MODE == 1) {
            if (k0 < 2048) { bph = bH0 + k0; bpl = bL0 + k0; }
            else {
                size_t o = (size_t)(1 * 16 + 1) * C1 + (k0 - 2048);  // center shift
                bph = pPH + o; bpl = pPL + o;
            }
        } else {
            int s = k0 >> 11, coff = k0 & 2047;
            int kh = s / 3, kw = s - kh * 3;
            size_t o = (size_t)(kh * 16 + kw) * C1 + coff;
            bph = pPH + o; bpl = pPL + o;
        }
        cpa16(d,                aph);   cpa16(d + 16,            aph + 8);
        cpa16(d + MATE * 2,     apl);   cpa16(d + MATE * 2 + 16, apl + 8);
        cpa16(d + MATE * 4,     bph);   cpa16(d + MATE * 4 + 16, bph + 8);
        cpa16(d + MATE * 6,     bpl);   cpa16(d + MATE * 6 + 16, bpl + 8);
        cpa_commit();
    };

    float acc[4][4][4];
#pragma unroll
    for (int i = 0; i < 4; i++)
#pragma unroll
        for (int j = 0; j < 4; j++)
#pragma unroll
            for (int u = 0; u < 4; u++) acc[i][j][u] = 0.f;

    load_stage(0, 0);

    for (int c = 0; c < NC; c++) {
        if (c + 1 < NC) {
            load_stage((c + 1) & 1, (c + 1) * 32);
            asm volatile("cp.async.wait_group 1;" ::: "memory");
        } else {
            asm volatile("cp.async.wait_group 0;" ::: "memory");
        }
        __syncthreads();

        const bf16* pAh = sm + (size_t)(c & 1) * STGE;
        const bf16* pAl = pAh + MATE;
        const bf16* pBh = pAh + 2 * MATE;
        const bf16* pBl = pAh + 3 * MATE;

#pragma unroll
        for (int kk = 0; kk < 32; kk += 16) {
            uint32_t aH[4][4], aL[4][4], bH[4][2], bL[4][2];
#pragma unroll
            for (int fm = 0; fm < 4; fm++) {
                int rb = (warp_m * 64 + fm * 16 + g) * SROW + kk + 2 * t4;
                aH[fm][0] = lds32(pAh, rb);
                aH[fm][1] = lds32(pAh, rb + 8 * SROW);
                aH[fm][2] = lds32(pAh, rb + 8);
                aH[fm][3] = lds32(pAh, rb + 8 * SROW + 8);
                aL[fm][0] = lds32(pAl, rb);
                aL[fm][1] = lds32(pAl, rb + 8 * SROW);
                aL[fm][2] = lds32(pAl, rb + 8);
                aL[fm][3] = lds32(pAl, rb + 8 * SROW + 8);
            }
#pragma unroll
            for (int fn = 0; fn < 4; fn++) {
                int nb = (warp_n * 32 + fn * 8 + g) * SROW + kk + 2 * t4;
                bH[fn][0] = lds32(pBh, nb);
                bH[fn][1] = lds32(pBh, nb + 8);
                bL[fn][0] = lds32(pBl, nb);
                bL[fn][1] = lds32(pBl, nb + 8);
            }
#pragma unroll
            for (int fm = 0; fm < 4; fm++)
#pragma unroll
                for (int fn = 0; fn < 4; fn++) {
                    mma_bf16(acc[fm][fn], aH[fm], bH[fn]);
                    mma_bf16(acc[fm][fn], aH[fm], bL[fn]);
                    mma_bf16(acc[fm][fn], aL[fm], bH[fn]);
                }
        }
        __syncthreads();
    }

    // ---- epilogue ----
    float sc[4][2], sh[4][2];
#pragma unroll
    for (int fm = 0; fm < 4; fm++)
#pragma unroll
        for (int hf = 0; hf < 2; hf++) {
            int m = m0 + warp_m * 64 + fm * 16 + g + hf * 8;
            if (MODE == 2) {
                float s = gamma[m] / sqrtf(var[m] + 1e-5f);
                sc[fm][hf] = s;
                sh[fm][hf] = beta[m] - mean[m] * s;
            } else {
                sc[fm][hf] = 1.f;
                sh[fm][hf] = bias[m];
            }
        }
#pragma unroll
    for (int fm = 0; fm < 4; fm++) {
#pragma unroll
        for (int fn = 0; fn < 4; fn++) {
#pragma unroll
            for (int u = 0; u < 4; u++) {
                int hf = u >> 1;
                int m = m0 + warp_m * 64 + fm * 16 + g + hf * 8;
                int col = col0 + warp_n * 32 + fn * 8 + 2 * t4 + (u & 1);
                int bo = col / NPIX, n = col - bo * NPIX;
                float vv = acc[fm][fn][u] * sc[fm][hf] + sh[fm][hf];
                if (MODE == 2) {
                    g_x[((size_t)bo * C2 + m) * NPIX + n] = fmaxf(vv, 0.f);
                } else if (MODE == 1) {
                    g_xb[((size_t)bo * C1 + m) * NPIX + n] = vv;
                } else {
                    float tv = r5[((size_t)bo * C1 + m) * NPIX + n] * vv;
                    bf16 hh, ll;
                    fsplit(tv, hh, ll);
                    size_t o = (size_t)col * C1 + m;
                    g_tTH[o] = hh; g_tTL[o] = ll;
                }
            }
        }
    }
}

// ===========================================================================
// EM attention (stage_num=3), one block per batch
// ===========================================================================
__global__ void __launch_bounds__(256) em_kernel(const float* __restrict__ mu0)
{
    const int b = blockIdx.x;
    const int tid = threadIdx.x, lane = tid & 31, wid = tid >> 5;
    const float* xb = g_x + (size_t)b * C2 * NPIX;

    __shared__ float mu[C2 * 8];
    __shared__ float z[NPIX * 8];
    __shared__ float norm[8], colsum[8];

    {
        float s = 0.f;
        for (int c = lane; c < C2; c += 32) { float v = mu0[c * 8 + wid]; s += v * v; }
#pragma unroll
        for (int o = 16; o; o >>= 1) s += __shfl_xor_sync(0xffffffffu, s, o);
        if (!lane) norm[wid] = sqrtf(s) + EPSF;
    }
    __syncthreads();
    for (int i = tid; i < C2 * 8; i += 256) mu[i] = mu0[i] / norm[i & 7];
    __syncthreads();

    for (int it = 0; it < 3; ++it) {
        if (tid < NPIX) {
            float l[8];
#pragma unroll
            for (int k = 0; k < 8; k++) l[k] = 0.f;
            for (int c = 0; c < C2; c++) {
                float xv = xb[c * NPIX + tid];
#pragma unroll
                for (int k = 0; k < 8; k++) l[k] += xv * mu[c * 8 + k];
            }
            float mx = l[0];
#pragma unroll
            for (int k = 1; k < 8; k++) mx = fmaxf(mx, l[k]);
            float e[8], s = 0.f;
#pragma unroll
            for (int k = 0; k < 8; k++) { e[k] = expf(l[k] - mx); s += e[k]; }
            float inv = 1.f / s;
#pragma unroll
            for (int k = 0; k < 8; k++) z[tid * 8 + k] = e[k] * inv;
        }
        __syncthreads();
        {
            float s = 0.f;
            for (int n = lane; n < NPIX; n += 32) s += z[n * 8 + wid];
#pragma unroll
            for (int o = 16; o; o >>= 1) s += __shfl_xor_sync(0xffffffffu, s, o);
            if (!lane) colsum[wid] = s + EPSF;
        }
        __syncthreads();
        for (int o = tid; o < C2 * 8; o += 256) {
            int c = o >> 3, k = o & 7;
            const float* xr = xb + c * NPIX;
            float s = 0.f;
            for (int n = 0; n < NPIX; n++) s += xr[n] * z[n * 8 + k];
            mu[o] = s / colsum[k];
        }
        __syncthreads();
        {
            float s = 0.f;
            for (int c = lane; c < C2; c += 32) { float v = mu[c * 8 + wid]; s += v * v; }
#pragma unroll
            for (int o = 16; o; o >>= 1) s += __shfl_xor_sync(0xffffffffu, s, o);
            if (!lane) norm[wid] = sqrtf(s) + EPSF;
        }
        __syncthreads();
        for (int i = tid; i < C2 * 8; i += 256) mu[i] /= norm[i & 7];
        __syncthreads();
    }
    if (tid < NPIX) {
        float zr[8];
#pragma unroll
        for (int k = 0; k < 8; k++) zr[k] = z[tid * 8 + k];
        float* x2o = g_x2 + (size_t)b * C2 * NPIX;
        for (int c = 0; c < C2; c++) {
            float s = 0.f;
#pragma unroll
            for (int k = 0; k < 8; k++) s += mu[c * 8 + k] * zr[k];
            float v = xb[c * NPIX + tid] + s;
            x2o[c * NPIX + tid] = fmaxf(v, 0.f);
        }
#pragma unroll
        for (int k = 0; k < 8; k++) g_zt[((size_t)b * 8 + k) * NPIX + tid] = zr[k];
    }
}

// ===========================================================================
// x1T: x1T[(b*196+h*14+v)][k*512+c] = sum_w x2[b,c,h*14+w] * zt[b,k,w*14+v]
// ===========================================================================
__global__ void __launch_bounds__(256) x1T_kernel()
{
    const int b = blockIdx.x, h = blockIdx.y;
    const int tid = threadIdx.x, lane = tid & 31, wid = tid >> 5;

    __shared__ float x2s[C2 * 14];
    __shared__ float zts[8 * NPIX];
    for (int i = tid; i < C2 * 14; i += 256) {
        int c = i / 14, w = i - c * 14;
        x2s[i] = g_x2[((size_t)b * C2 + c) * NPIX + h * 14 + w];
    }
    for (int i = tid; i < 8 * NPIX; i += 256) zts[i] = g_zt[(size_t)b * 8 * NPIX + i];
    __syncthreads();

    for (int ci = 0; ci < 2; ci++) {
        const int c = wid * 64 + ci * 32 + lane;
        float xv[14];
#pragma unroll
        for (int w = 0; w < 14; w++) xv[w] = x2s[c * 14 + w];
#pragma unroll
        for (int k = 0; k < 8; k++) {
            float out[14];
#pragma unroll
            for (int v = 0; v < 14; v++) out[v] = 0.f;
#pragma unroll
            for (int w = 0; w < 14; w++) {
                float a = xv[w];
                const float* zp = zts + k * NPIX + w * 14;
#pragma unroll
                for (int v = 0; v < 14; v++) out[v] += a * zp[v];
            }
#pragma unroll
            for (int v = 0; v < 14; v++) {
                bf16 hh, ll;
                fsplit(out[v], hh, ll);
                size_t o = ((size_t)b * NPIX + h * 14 + v) * K4 + k * C2 + c;
                g_x1TH[o] = hh; g_x1TL[o] = ll;
            }
        }
    }
}

// ===========================================================================
// downconv 2048->32 (4 output channels per block)
// ===========================================================================
__global__ void __launch_bounds__(256) down_kernel(
    const float* __restrict__ dw, const float* __restrict__ db)
{
    const int b = blockIdx.x, jg = blockIdx.y, tid = threadIdx.x;
    __shared__ float ws[4 * 2048];
    for (int i = tid; i < 4 * 2048; i += 256) ws[i] = dw[jg * 4 * 2048 + i];
    __syncthreads();
    if (tid < NPIX) {
        float acc[4];
#pragma unroll
        for (int j = 0; j < 4; j++) acc[j] = db[jg * 4 + j];
        const float* xp = g_xb + (size_t)b * C1 * NPIX + tid;
        for (int c = 0; c < 2048; c++) {
            float v = xp[(size_t)c * NPIX];
#pragma unroll
            for (int j = 0; j < 4; j++) acc[j] += ws[j * 2048 + c] * v;
        }
#pragma unroll
        for (int j = 0; j < 4; j++)
            g_xd[((size_t)b * 32 + jg * 4 + j) * NPIX + tid] = acc[j];
    }
}

// ===========================================================================
// GAP + class-wise pools -> xg (output[0:512]) and xc map
// ===========================================================================
__global__ void __launch_bounds__(256) pool_kernel(float* __restrict__ dout)
{
    const int b = blockIdx.x, tid = threadIdx.x;
    __shared__ float gap[32];
    __shared__ float xgs[8];
    if (tid < 32) {
        const float* p = g_xd + ((size_t)b * 32 + tid) * NPIX;
        float s = 0.f;
        for (int n = 0; n < NPIX; n++) s += p[n];
        gap[tid] = s * (1.f / NPIX);
    }
    __syncthreads();
    if (tid < 8) {
        float g = 0.25f * (gap[4 * tid] + gap[4 * tid + 1] + gap[4 * tid + 2] + gap[4 * tid + 3]);
        xgs[tid] = g;
        dout[b * 8 + tid] = g;
    }
    __syncthreads();
    if (tid < NPIX) {
        const float* p = g_xd + (size_t)b * 32 * NPIX + tid;
        float s = 0.f;
#pragma unroll
        for (int pp = 0; pp < 8; pp++) {
            float cp = 0.25f * (p[(4 * pp + 0) * NPIX] + p[(4 * pp + 1) * NPIX] +
                                p[(4 * pp + 2) * NPIX] + p[(4 * pp + 3) * NPIX]);
            s += cp * xgs[pp];
        }
        g_xc[b * NPIX + tid] = s * 0.125f;
    }
}

// ===========================================================================
// cls head -> out2 (output[512:1024])
// ===========================================================================
__global__ void __launch_bounds__(256) out2_kernel(
    const float* __restrict__ r5, const float* __restrict__ cw,
    const float* __restrict__ cb, float* __restrict__ dout)
{
    const int b = blockIdx.x, tid = threadIdx.x, lane = tid & 31, wid = tid >> 5;
    __shared__ float xcs[NPIX];
    for (int i = tid; i < NPIX; i += 256) xcs[i] = g_xc[b * NPIX + i];
    __syncthreads();
    const float inv = 1.f / NPIX;
    float accL = 0.f;
    for (int c = wid; c < 2048; c += 8) {
        const float* rp = r5 + ((size_t)b * C1 + c) * NPIX;
        float s1 = 0.f, s2 = 0.f;
        for (int n = lane; n < NPIX; n += 32) { float v = rp[n]; s1 += v; s2 += v * xcs[n]; }
#pragma unroll
        for (int o = 16; o; o >>= 1) {
            s1 += __shfl_xor_sync(0xffffffffu, s1, o);
            s2 += __shfl_xor_sync(0xffffffffu, s2, o);
        }
        if (lane < 8)
            accL += cw[lane * 4096 + c] * s1 * inv + cw[lane * 4096 + 2048 + c] * s2 * inv;
    }
    __shared__ float wsum[8][8];
    if (lane < 8) wsum[wid][lane] = accL;
    __syncthreads();
    if (tid < 8) {
        float s = cb[tid];
#pragma unroll
        for (int w2 = 0; w2 < 8; w2++) s += wsum[w2][tid];
        dout[512 + b * 8 + tid] = s;
    }
}

// ===========================================================================
extern "C" void kernel_launch(void* const* d_in, const int* in_sizes, int n_in,
                              void* d_out, int out_size)
{
    const float* r5   = (const float*)d_in[0];
    const float* fc0  = (const float*)d_in[1];
    const float* bng  = (const float*)d_in[2];
    const float* bnb  = (const float*)d_in[3];
    const float* bnm  = (const float*)d_in[4];
    const float* bnv  = (const float*)d_in[5];
    const float* mu0  = (const float*)d_in[6];
    const float* c4w  = (const float*)d_in[7];
    const float* c4b  = (const float*)d_in[8];
    const float* dw   = (const float*)d_in[9];
    const float* db   = (const float*)d_in[10];
    const float* cw   = (const float*)d_in[11];
    const float* cb   = (const float*)d_in[12];
    float* out = (float*)d_out;

    static int smem_set = 0;
    if (!smem_set) {
        cudaFuncSetAttribute(mma_gemm_kernel<0>, cudaFuncAttributeMaxDynamicSharedMemorySize, SM_BYTES);
        cudaFuncSetAttribute(mma_gemm_kernel<1>, cudaFuncAttributeMaxDynamicSharedMemorySize, SM_BYTES);
        cudaFuncSetAttribute(mma_gemm_kernel<2>, cudaFuncAttributeMaxDynamicSharedMemorySize, SM_BYTES);
        smem_set = 1;
    }

    bf16 *fcH, *fcL, *c4H, *c4L;
    cudaGetSymbolAddress((void**)&fcH, g_fcH);
    cudaGetSymbolAddress((void**)&fcL, g_fcL);
    cudaGetSymbolAddress((void**)&c4H, g_c4H);
    cudaGetSymbolAddress((void**)&c4L, g_c4L);

    // ---- prep: split weights + padded transpose of r5 ----
    fc0_perm_kernel<<<2048, 256>>>(fc0);
    cvt_split_kernel<<<2048, 256>>>(c4w, c4H, c4L, (size_t)C1 * K4);
    r5P_zero_kernel<<<1024, 256>>>();
    r5P_fill_kernel<<<dim3(64, 64, 7), dim3(32, 8)>>>(r5);

    // ---- conv3x3 + BN + ReLU ----
    mma_gemm_kernel<2><<<dim3(98, 4), 256, SM_BYTES>>>(fcH, fcL, r5, nullptr, bng, bnb, bnm, bnv);
    em_kernel<<<64, 256>>>(mu0);
    x1T_kernel<<<dim3(64, 14), 256>>>();
    // ---- conv4 pass 1 & 2 ----
    mma_gemm_kernel<0><<<dim3(98, 16), 256, SM_BYTES>>>(c4H, c4L, r5, c4b, nullptr, nullptr, nullptr, nullptr);
    mma_gemm_kernel<1><<<dim3(98, 16), 256, SM_BYTES>>>(c4H, c4L, r5, c4b, nullptr, nullptr, nullptr, nullptr);
    down_kernel<<<dim3(64, 8), 256>>>(dw, db);
    pool_kernel<<<64, 256>>>(out);
    out2_kernel<<<64, 256>>>(r5, cw, cb, out);
}